// round 1
// baseline (speedup 1.0000x reference)
#include <cuda_runtime.h>
#include <math_constants.h>

#define BB 2
#define NN 32768
#define MM 4096
#define CC 128
#define OUTC 128
#define INC 131
#define HPAD 132

// Scratch (allocation-free: __device__ globals)
__device__ float4 g_skey[BB * MM];                       // (-2sx,-2sy,-2sz,|s|^2)
__device__ float  g_h[(size_t)BB * NN * HPAD];           // [interp(128) | x(3) | 0]

// ---------------------------------------------------------------------------
// Kernel 0: precompute sampled-point keys
// ---------------------------------------------------------------------------
__global__ void prep_skey_kernel(const float* __restrict__ sx) {
    int i = blockIdx.x * blockDim.x + threadIdx.x;
    if (i < BB * MM) {
        float s0 = sx[i * 3 + 0];
        float s1 = sx[i * 3 + 1];
        float s2 = sx[i * 3 + 2];
        g_skey[i] = make_float4(-2.f * s0, -2.f * s1, -2.f * s2,
                                s0 * s0 + s1 * s1 + s2 * s2);
    }
}

// ---------------------------------------------------------------------------
// Kernel 1: brute-force 3-NN + feature interpolation, writes h rows to g_h
//   block = 256 threads, 256 queries/block, sampled keys cached in SMEM
// ---------------------------------------------------------------------------
__global__ void __launch_bounds__(256) knn_interp_kernel(
    const float* __restrict__ x, const float* __restrict__ feat) {
    extern __shared__ float4 sk[];   // MM float4 = 64KB

    const int q0 = blockIdx.x * 256;     // global query base (doesn't straddle batch)
    const int b  = q0 / NN;

    for (int i = threadIdx.x; i < MM; i += 256)
        sk[i] = g_skey[b * MM + i];
    __syncthreads();

    const int q = q0 + threadIdx.x;
    const float x0 = x[q * 3 + 0];
    const float x1 = x[q * 3 + 1];
    const float x2 = x[q * 3 + 2];

    // running top-3 (smallest key ~ smallest distance); strict < keeps lower idx on tie
    float m0 = CUDART_INF_F, m1 = CUDART_INF_F, m2 = CUDART_INF_F;
    int   i0 = 0, i1 = 0, i2 = 0;

#pragma unroll 4
    for (int j = 0; j < MM; j++) {
        float4 s = sk[j];   // uniform address -> broadcast LDS.128
        float v = fmaf(s.x, x0, fmaf(s.y, x1, fmaf(s.z, x2, s.w)));
        if (v < m2) {
            if (v < m1) {
                m2 = m1; i2 = i1;
                if (v < m0) { m1 = m0; i1 = i0; m0 = v; i0 = j; }
                else        { m1 = v;  i1 = j; }
            } else { m2 = v; i2 = j; }
        }
    }

    __syncthreads();                       // done reading sk; reuse smem for indices
    int* idxs = (int*)sk;
    idxs[threadIdx.x * 3 + 0] = i0;
    idxs[threadIdx.x * 3 + 1] = i1;
    idxs[threadIdx.x * 3 + 2] = i2;
    __syncwarp();                          // each warp only reads its own 32 entries

    // warp-cooperative gather: lane = 4-channel chunk -> fully coalesced
    const int lane = threadIdx.x & 31;
    const int wq0  = threadIdx.x & ~31;
    const float4* F = (const float4*)feat;   // features as float4 rows of 32

    for (int i = 0; i < 32; i++) {
        const int t  = wq0 + i;
        const int gq = q0 + t;
        const int j0 = idxs[t * 3 + 0];
        const int j1 = idxs[t * 3 + 1];
        const int j2 = idxs[t * 3 + 2];

        float4 f0 = F[(size_t)(b * MM + j0) * 32 + lane];
        float4 f1 = F[(size_t)(b * MM + j1) * 32 + lane];
        float4 f2 = F[(size_t)(b * MM + j2) * 32 + lane];

        float4 a;
        a.x = (f0.x + f1.x + f2.x) * (1.f / 3.f);
        a.y = (f0.y + f1.y + f2.y) * (1.f / 3.f);
        a.z = (f0.z + f1.z + f2.z) * (1.f / 3.f);
        a.w = (f0.w + f1.w + f2.w) * (1.f / 3.f);

        *(float4*)&g_h[(size_t)gq * HPAD + lane * 4] = a;

        if (lane == 0) {
            float c0 = x[gq * 3 + 0];
            float c1 = x[gq * 3 + 1];
            float c2 = x[gq * 3 + 2];
            *(float4*)&g_h[(size_t)gq * HPAD + 128] = make_float4(c0, c1, c2, 0.f);
        }
    }
}

// ---------------------------------------------------------------------------
// Kernel 2: fused MLP (131->128 relu -> 128), transposed coalesced output
//   block = 128 threads (thread = out channel), tile = 64 points
// ---------------------------------------------------------------------------
__global__ void __launch_bounds__(128) mlp_kernel(
    const float* __restrict__ w1, const float* __restrict__ b1,
    const float* __restrict__ w2, const float* __restrict__ b2,
    float* __restrict__ out) {
    extern __shared__ float sm[];
    float* w1s = sm;                    // [132][128] transposed+permuted
    float* w2s = w1s + HPAD * 128;      // [128][128] transposed
    float* hs  = w2s + 128 * 128;       // [64][132]  (reused as stage-2 out)
    float* t1  = hs  + 64 * HPAD;       // [64][132]  stage-1 out

    const int tid = threadIdx.x;
    const int o   = tid;

    // stage weights (each thread walks its own row -> L1-cached sequential reads)
    {
        const float* wr1 = w1 + o * INC;
        for (int k = 0; k < HPAD; k++) {
            float v;
            if (k < 128)      v = wr1[3 + k];     // interp channels
            else if (k < 131) v = wr1[k - 128];   // coords
            else              v = 0.f;            // pad
            w1s[k * 128 + o] = v;
        }
        const float* wr2 = w2 + o * 128;
        for (int k = 0; k < 128; k++)
            w2s[k * 128 + o] = wr2[k];
    }

    // load h tile (64 points x 132), coalesced float4
    const int p0 = blockIdx.x * 64;       // global point base
    const int b  = p0 / NN;
    const int n0 = p0 - b * NN;
    {
        float4* hs4 = (float4*)hs;
        const float4* gh4 = (const float4*)(g_h + (size_t)p0 * HPAD);
        for (int i = tid; i < 64 * (HPAD / 4); i += 128)
            hs4[i] = gh4[i];
    }
    __syncthreads();

    // ---- stage 1: t1 = relu(h @ w1^T + b1) ----
    float acc[64];
    {
        const float bias = b1[o];
#pragma unroll
        for (int p = 0; p < 64; p++) acc[p] = bias;

        for (int k = 0; k < HPAD; k += 4) {
            const float wv0 = w1s[(k + 0) * 128 + o];
            const float wv1 = w1s[(k + 1) * 128 + o];
            const float wv2 = w1s[(k + 2) * 128 + o];
            const float wv3 = w1s[(k + 3) * 128 + o];
#pragma unroll
            for (int p = 0; p < 64; p++) {
                float4 hv = *(const float4*)&hs[p * HPAD + k];
                acc[p] = fmaf(wv0, hv.x, acc[p]);
                acc[p] = fmaf(wv1, hv.y, acc[p]);
                acc[p] = fmaf(wv2, hv.z, acc[p]);
                acc[p] = fmaf(wv3, hv.w, acc[p]);
            }
        }
#pragma unroll
        for (int p = 0; p < 64; p++)
            t1[p * HPAD + o] = fmaxf(acc[p], 0.f);
    }
    __syncthreads();

    // ---- stage 2: out = t1 @ w2^T + b2, result into hs (transposed staging) ----
    {
        const float bias = b2[o];
#pragma unroll
        for (int p = 0; p < 64; p++) acc[p] = bias;

        for (int k = 0; k < 128; k += 4) {
            const float wv0 = w2s[(k + 0) * 128 + o];
            const float wv1 = w2s[(k + 1) * 128 + o];
            const float wv2 = w2s[(k + 2) * 128 + o];
            const float wv3 = w2s[(k + 3) * 128 + o];
#pragma unroll
            for (int p = 0; p < 64; p++) {
                float4 tv = *(const float4*)&t1[p * HPAD + k];
                acc[p] = fmaf(wv0, tv.x, acc[p]);
                acc[p] = fmaf(wv1, tv.y, acc[p]);
                acc[p] = fmaf(wv2, tv.z, acc[p]);
                acc[p] = fmaf(wv3, tv.w, acc[p]);
            }
        }
#pragma unroll
        for (int p = 0; p < 64; p++)
            hs[p * HPAD + o] = acc[p];
    }
    __syncthreads();

    // coalesced transposed write: out[b][oc][n0+p]
    {
        float* ob = out + (size_t)b * OUTC * NN + n0;
        for (int idx = tid; idx < 128 * 64; idx += 128) {
            const int oc = idx >> 6;
            const int p  = idx & 63;
            ob[(size_t)oc * NN + p] = hs[p * HPAD + oc];
        }
    }
}

// ---------------------------------------------------------------------------
extern "C" void kernel_launch(void* const* d_in, const int* in_sizes, int n_in,
                              void* d_out, int out_size) {
    const float* x   = (const float*)d_in[0];   // [B,N,3]
    const float* sx  = (const float*)d_in[1];   // [B,M,3]
    const float* ft  = (const float*)d_in[2];   // [B,M,C]
    const float* w1  = (const float*)d_in[3];   // [128,131]
    const float* b1  = (const float*)d_in[4];   // [128]
    const float* w2  = (const float*)d_in[5];   // [128,128]
    const float* b2  = (const float*)d_in[6];   // [128]
    float* out = (float*)d_out;                 // [B,128,N]

    const int knn_smem = MM * sizeof(float4);                                   // 64 KB
    const int mlp_smem = (HPAD * 128 + 128 * 128 + 64 * HPAD + 64 * HPAD) * 4;  // ~196 KB

    cudaFuncSetAttribute(knn_interp_kernel,
                         cudaFuncAttributeMaxDynamicSharedMemorySize, knn_smem);
    cudaFuncSetAttribute(mlp_kernel,
                         cudaFuncAttributeMaxDynamicSharedMemorySize, mlp_smem);

    prep_skey_kernel<<<(BB * MM + 255) / 256, 256>>>(sx);
    knn_interp_kernel<<<(BB * NN) / 256, 256, knn_smem>>>(x, ft);
    mlp_kernel<<<(BB * NN) / 64, 128, mlp_smem>>>(w1, b1, w2, b2, out);
}

// round 2
// speedup vs baseline: 1.0931x; 1.0931x over previous
#include <cuda_runtime.h>
#include <math_constants.h>

#define BB 2
#define NN 32768
#define MM 4096
#define CC 128
#define OUTC 128
#define INC 131
#define HPAD 132
#define M2 (MM / 2)

typedef unsigned long long ull;

// ---------------------------------------------------------------------------
// Scratch (__device__ globals: allocation-free)
// ---------------------------------------------------------------------------
__device__ __align__(16) float4 g_skA[BB * M2];   // (-2sx_j, -2sx_j1, -2sy_j, -2sy_j1)
__device__ __align__(16) float4 g_skB[BB * M2];   // (-2sz_j, -2sz_j1, |s_j|^2, |s_j1|^2)
__device__ __align__(16) float  g_w1q[33 * 128 * 4];  // [kq][o][4] permuted w1
__device__ __align__(16) float  g_w2q[32 * 128 * 4];  // [kq][o][4] w2
__device__ int g_idx[BB * NN * 3];

// ---------------------------------------------------------------------------
// f32x2 helpers (FFMA2 is PTX-only; ptxas never auto-fuses)
// ---------------------------------------------------------------------------
__device__ __forceinline__ ull fma2(ull a, ull b, ull c) {
    ull d;
    asm("fma.rn.f32x2 %0, %1, %2, %3;" : "=l"(d) : "l"(a), "l"(b), "l"(c));
    return d;
}
__device__ __forceinline__ ull pack2(float a, float b) {
    ull r;
    asm("mov.b64 %0, {%1, %2};" : "=l"(r)
        : "r"(__float_as_uint(a)), "r"(__float_as_uint(b)));
    return r;
}
__device__ __forceinline__ float2 unpack2(ull v) {
    unsigned int lo, hi;
    asm("mov.b64 {%0, %1}, %2;" : "=r"(lo), "=r"(hi) : "l"(v));
    return make_float2(__uint_as_float(lo), __uint_as_float(hi));
}

// ---------------------------------------------------------------------------
// Kernel 0: prep — paired sampled-point keys + transposed/quadded weights
// ---------------------------------------------------------------------------
#define SK_W (BB * M2)
#define W1_W (33 * 128)
#define W2_W (32 * 128)

__global__ void prep_kernel(const float* __restrict__ sx,
                            const float* __restrict__ w1,
                            const float* __restrict__ w2) {
    int i = blockIdx.x * blockDim.x + threadIdx.x;
    if (i < SK_W) {
        int b = i / M2, j2 = i % M2;
        const float* p = sx + (size_t)(b * MM + 2 * j2) * 3;
        float a0 = p[0], a1 = p[1], a2 = p[2];
        float c0 = p[3], c1 = p[4], c2 = p[5];
        g_skA[i] = make_float4(-2.f * a0, -2.f * c0, -2.f * a1, -2.f * c1);
        g_skB[i] = make_float4(-2.f * a2, -2.f * c2,
                               a0 * a0 + a1 * a1 + a2 * a2,
                               c0 * c0 + c1 * c1 + c2 * c2);
    } else if (i < SK_W + W1_W) {
        int t = i - SK_W;
        int kq = t >> 7, o = t & 127;
        float v[4];
#pragma unroll
        for (int q = 0; q < 4; q++) {
            int k = kq * 4 + q;
            if (k < 128)      v[q] = w1[o * INC + 3 + k];      // interp channels
            else if (k < 131) v[q] = w1[o * INC + (k - 128)];  // coords
            else              v[q] = 0.f;                      // pad
        }
        *(float4*)&g_w1q[t * 4] = make_float4(v[0], v[1], v[2], v[3]);
    } else if (i < SK_W + W1_W + W2_W) {
        int t = i - SK_W - W1_W;
        int kq = t >> 7, o = t & 127;
        const float* wr = w2 + o * 128 + kq * 4;
        *(float4*)&g_w2q[t * 4] = make_float4(wr[0], wr[1], wr[2], wr[3]);
    }
}

// ---------------------------------------------------------------------------
// Kernel 1: brute-force 3-NN, paired candidates via f32x2, writes g_idx
//   block = 128 threads = 128 queries
// ---------------------------------------------------------------------------
__global__ void __launch_bounds__(128) knn_kernel(const float* __restrict__ x) {
    extern __shared__ float4 sm4[];
    float4* skA = sm4;            // 2048 float4 = 32KB
    float4* skB = sm4 + M2;       // 32KB

    const int q0 = blockIdx.x * 128;
    const int b  = q0 / NN;

    for (int i = threadIdx.x; i < M2; i += 128) {
        skA[i] = g_skA[b * M2 + i];
        skB[i] = g_skB[b * M2 + i];
    }
    __syncthreads();

    const int q = q0 + threadIdx.x;
    const float x0 = x[q * 3 + 0];
    const float x1 = x[q * 3 + 1];
    const float x2 = x[q * 3 + 2];
    const ull x00 = pack2(x0, x0);
    const ull x11 = pack2(x1, x1);
    const ull x22 = pack2(x2, x2);

    float m0 = CUDART_INF_F, m1 = CUDART_INF_F, m2v = CUDART_INF_F;
    int   i0 = 0, i1 = 0, i2 = 0;

    const ulonglong2* A2 = (const ulonglong2*)skA;
    const ulonglong2* B2 = (const ulonglong2*)skB;

#pragma unroll 4
    for (int j2 = 0; j2 < M2; j2++) {
        ulonglong2 A = A2[j2];           // {sx pair, sy pair}
        ulonglong2 Bv = B2[j2];          // {sz pair, norm pair}
        ull v = fma2(Bv.x, x22, Bv.y);
        v = fma2(A.y, x11, v);
        v = fma2(A.x, x00, v);
        float2 vv = unpack2(v);
        float vm = fminf(vv.x, vv.y);
        if (vm < m2v) {                  // rare path
            // lo candidate (index 2*j2) first — preserves tie order
            if (vv.x < m2v) {
                float v1 = vv.x; int j = 2 * j2;
                if (v1 < m1) {
                    m2v = m1; i2 = i1;
                    if (v1 < m0) { m1 = m0; i1 = i0; m0 = v1; i0 = j; }
                    else         { m1 = v1; i1 = j; }
                } else { m2v = v1; i2 = j; }
            }
            if (vv.y < m2v) {
                float v1 = vv.y; int j = 2 * j2 + 1;
                if (v1 < m1) {
                    m2v = m1; i2 = i1;
                    if (v1 < m0) { m1 = m0; i1 = i0; m0 = v1; i0 = j; }
                    else         { m1 = v1; i1 = j; }
                } else { m2v = v1; i2 = j; }
            }
        }
    }

    g_idx[q * 3 + 0] = i0;
    g_idx[q * 3 + 1] = i1;
    g_idx[q * 3 + 2] = i2;
}

// ---------------------------------------------------------------------------
// Kernel 2: fused gather + MLP (131->128 relu ->128), f32x2, coalesced output
//   block = 256 threads: o = tid&127 (out channel), half = tid>>7 (32 points)
//   tile = 64 points
// ---------------------------------------------------------------------------
__global__ void __launch_bounds__(256) mlp_kernel(
    const float* __restrict__ x, const float* __restrict__ feat,
    const float* __restrict__ b1, const float* __restrict__ b2,
    float* __restrict__ out) {
    extern __shared__ float sm[];
    float* hs = sm;               // [64][132]
    float* t1 = sm + 64 * HPAD;   // [64][132]

    const int tid  = threadIdx.x;
    const int o    = tid & 127;
    const int half = tid >> 7;
    const int p0   = blockIdx.x * 64;
    const int b    = p0 / NN;
    const int n0   = p0 - b * NN;

    // ---- gather h tile: 8 warps x 8 points, lane = float4 channel chunk ----
    {
        const int wid  = tid >> 5;
        const int lane = tid & 31;
        const float4* F = (const float4*)feat;
#pragma unroll
        for (int t = 0; t < 8; t++) {
            const int pt = wid * 8 + t;
            const int gq = p0 + pt;
            const int j0 = g_idx[gq * 3 + 0];
            const int j1 = g_idx[gq * 3 + 1];
            const int j2 = g_idx[gq * 3 + 2];
            float4 f0 = F[(size_t)(b * MM + j0) * 32 + lane];
            float4 f1 = F[(size_t)(b * MM + j1) * 32 + lane];
            float4 f2 = F[(size_t)(b * MM + j2) * 32 + lane];
            float4 a;
            a.x = (f0.x + f1.x + f2.x) * (1.f / 3.f);
            a.y = (f0.y + f1.y + f2.y) * (1.f / 3.f);
            a.z = (f0.z + f1.z + f2.z) * (1.f / 3.f);
            a.w = (f0.w + f1.w + f2.w) * (1.f / 3.f);
            *(float4*)&hs[pt * HPAD + lane * 4] = a;
            if (lane == 0) {
                *(float4*)&hs[pt * HPAD + 128] =
                    make_float4(x[gq * 3 + 0], x[gq * 3 + 1], x[gq * 3 + 2], 0.f);
            }
        }
    }
    __syncthreads();

    const int pb = half * 32;
    ull acc[32];

    // ---- stage 1: t1 = relu(h @ w1^T + b1), 33 k-quads ----
    {
#pragma unroll
        for (int p = 0; p < 32; p++) acc[p] = 0ull;

        const ulonglong2* w1q = (const ulonglong2*)g_w1q;
        for (int kq = 0; kq < 33; kq++) {
            ulonglong2 w = w1q[kq * 128 + o];   // coalesced LDG.128
#pragma unroll
            for (int p = 0; p < 32; p++) {
                ulonglong2 h = *(const ulonglong2*)&hs[(pb + p) * HPAD + kq * 4];
                acc[p] = fma2(w.x, h.x, acc[p]);
                acc[p] = fma2(w.y, h.y, acc[p]);
            }
        }
        const float bias = b1[o];
#pragma unroll
        for (int p = 0; p < 32; p++) {
            float2 s = unpack2(acc[p]);
            t1[(pb + p) * HPAD + o] = fmaxf(s.x + s.y + bias, 0.f);
        }
    }
    __syncthreads();

    // ---- stage 2: out = t1 @ w2^T + b2, 32 k-quads ----
    {
#pragma unroll
        for (int p = 0; p < 32; p++) acc[p] = 0ull;

        const ulonglong2* w2q = (const ulonglong2*)g_w2q;
        for (int kq = 0; kq < 32; kq++) {
            ulonglong2 w = w2q[kq * 128 + o];
#pragma unroll
            for (int p = 0; p < 32; p++) {
                ulonglong2 h = *(const ulonglong2*)&t1[(pb + p) * HPAD + kq * 4];
                acc[p] = fma2(w.x, h.x, acc[p]);
                acc[p] = fma2(w.y, h.y, acc[p]);
            }
        }
        const float bias = b2[o];
        float* s_o = hs;   // reuse, stride 129 (conflict-free transpose read)
#pragma unroll
        for (int p = 0; p < 32; p++) {
            float2 s = unpack2(acc[p]);
            s_o[(pb + p) * 129 + o] = s.x + s.y + bias;
        }
    }
    __syncthreads();

    // ---- coalesced transposed store: out[b][oc][n0+p] ----
    {
        const float* s_o = hs;
        float* ob = out + (size_t)b * OUTC * NN + n0;
        for (int idx = tid; idx < 128 * 64; idx += 256) {
            const int oc = idx >> 6;
            const int p  = idx & 63;
            ob[(size_t)oc * NN + p] = s_o[p * 129 + oc];
        }
    }
}

// ---------------------------------------------------------------------------
extern "C" void kernel_launch(void* const* d_in, const int* in_sizes, int n_in,
                              void* d_out, int out_size) {
    const float* x   = (const float*)d_in[0];   // [B,N,3]
    const float* sx  = (const float*)d_in[1];   // [B,M,3]
    const float* ft  = (const float*)d_in[2];   // [B,M,C]
    const float* w1  = (const float*)d_in[3];   // [128,131]
    const float* b1  = (const float*)d_in[4];   // [128]
    const float* w2  = (const float*)d_in[5];   // [128,128]
    const float* b2  = (const float*)d_in[6];   // [128]
    float* out = (float*)d_out;                 // [B,128,N]

    const int knn_smem = MM * sizeof(float4);            // 64 KB (skA+skB)
    const int mlp_smem = 2 * 64 * HPAD * sizeof(float);  // 67.6 KB

    cudaFuncSetAttribute(knn_kernel,
                         cudaFuncAttributeMaxDynamicSharedMemorySize, knn_smem);
    cudaFuncSetAttribute(mlp_kernel,
                         cudaFuncAttributeMaxDynamicSharedMemorySize, mlp_smem);

    const int prep_threads = SK_W + W1_W + W2_W;
    prep_kernel<<<(prep_threads + 127) / 128, 128>>>(sx, w1, w2);
    knn_kernel<<<(BB * NN) / 128, 128, knn_smem>>>(x);
    mlp_kernel<<<(BB * NN) / 64, 256, mlp_smem>>>(x, ft, b1, b2, out);
}